// round 1
// baseline (speedup 1.0000x reference)
#include <cuda_runtime.h>
#include <math.h>

// Problem dims (fixed by the dataset)
#define NB 4
#define CC 256
#define TT 16
#define HH 56
#define WW 56
#define KK 16
#define TP 8
#define HP 28
#define WP 28
#define PLANE (TT*HH*WW)        // 50176, channel stride in vw
#define OPLANE (TP*HP*WP)       // 6272, channel stride in out

// Scratch: exp map, [N, T, H, W]
__device__ float g_emap[NB * TT * HH * WW];

__device__ __forceinline__ unsigned long long fma2(unsigned long long a,
                                                   unsigned long long b,
                                                   unsigned long long c) {
    unsigned long long d;
    asm("fma.rn.f32x2 %0, %1, %2, %3;" : "=l"(d) : "l"(a), "l"(b), "l"(c));
    return d;
}

__device__ __forceinline__ float lo32(unsigned long long v) {
    return __uint_as_float((unsigned)v);
}
__device__ __forceinline__ float hi32(unsigned long long v) {
    return __uint_as_float((unsigned)(v >> 32));
}

// ---------------------------------------------------------------------------
// Kernel 1: emap[n,t,h,w] = exp( max_k( sum_c w[n,k,c]*vw[n,c,t,h,w] ) / 16 )
// grid (H/4=14, T=16, N=4), block (32,4): one warp per (n,t,h) row.
// Each lane handles a pair of w positions (2*lane, 2*lane+1) packed in f32x2.
// ---------------------------------------------------------------------------
__global__ __launch_bounds__(128) void emap_kernel(const float* __restrict__ vw,
                                                   const float* __restrict__ wmat) {
    __shared__ unsigned long long wsp[CC * KK];  // [c][k], each {s,s} packed

    const int n = blockIdx.z;
    const int t = blockIdx.y;
    const int h = blockIdx.x * 4 + threadIdx.y;
    const int tid = threadIdx.y * 32 + threadIdx.x;

    // Load weights for this n into smem, duplicated into both f32x2 halves.
    const float* wn = wmat + (size_t)n * KK * CC;   // layout [k][c]
    for (int j = tid; j < KK * CC; j += 128) {
        int k = j >> 8;        // j = k*256 + c
        int c = j & 255;
        unsigned int si = __float_as_uint(wn[j]);
        wsp[c * KK + k] = ((unsigned long long)si << 32) | si;
    }
    __syncthreads();

    const int lane = threadIdx.x;
    if (lane >= 28) return;  // 28 pairs cover W=56

    // c=0 address for this (n,t,h) row at w = 2*lane
    size_t base = ((size_t)n * CC * TT + t) * (HH * WW) + (size_t)h * WW + 2 * lane;
    const unsigned long long* src = (const unsigned long long*)(vw + base);

    unsigned long long acc[KK];
#pragma unroll
    for (int k = 0; k < KK; k++) acc[k] = 0ull;

    const ulonglong2* wv = (const ulonglong2*)wsp;

#pragma unroll 4
    for (int c = 0; c < CC; c++) {
        unsigned long long x = __ldg(src);
        src += PLANE / 2;
#pragma unroll
        for (int kk = 0; kk < KK / 2; kk++) {
            ulonglong2 wp = wv[c * (KK / 2) + kk];
            acc[2 * kk]     = fma2(wp.x, x, acc[2 * kk]);
            acc[2 * kk + 1] = fma2(wp.y, x, acc[2 * kk + 1]);
        }
    }

    float m0 = -3.4e38f, m1 = -3.4e38f;
#pragma unroll
    for (int k = 0; k < KK; k++) {
        m0 = fmaxf(m0, lo32(acc[k]));
        m1 = fmaxf(m1, hi32(acc[k]));
    }
    // sqrt(C) = 16 exactly
    float e0 = expf(m0 * 0.0625f);
    float e1 = expf(m1 * 0.0625f);

    size_t eidx = (((size_t)n * TT + t) * HH + h) * WW + 2 * lane;
    *(float2*)(g_emap + eidx) = make_float2(e0, e1);
}

// ---------------------------------------------------------------------------
// Kernel 2: out[n,c,t',h',w'] = sum_{window} vw*emap / sum_{window} emap
// Window: t in 2t'-1..2t'+1, h in 2h'-1..2h'+1, w in 2w'-1..2w'+1 (zero pad).
// grid (HP=28, TP=8, N=4), block (32,8): lane = w', y = channel group.
// Per lane: 27 emap weights hoisted to registers (channel-invariant);
// inner loop does 9 x LDG.64 (w-pair) + shfl_up for the w-1 element.
// ---------------------------------------------------------------------------
__global__ __launch_bounds__(256) void pool_kernel(const float* __restrict__ vw,
                                                   float* __restrict__ out) {
    const int n  = blockIdx.z;
    const int tp = blockIdx.y;
    const int hp = blockIdx.x;
    const int lane = threadIdx.x;
    const int wl = lane < 27 ? lane : 27;  // clamp for safe address math
    const bool act = (lane < 28);

    float ewm[9];                 // weight for w = 2w'-1
    unsigned long long ewp[9];    // packed weights for w = 2w', 2w'+1
    int rowoff[9];                // (t*H + h)*W offsets (clamped)
    float dsum = 0.f;

#pragma unroll
    for (int dt = 0; dt < 3; dt++) {
#pragma unroll
        for (int dh = 0; dh < 3; dh++) {
            const int r = dt * 3 + dh;
            const int t = 2 * tp - 1 + dt;   // max 15, only -1 possible OOB
            const int h = 2 * hp - 1 + dh;   // max 55, only -1 possible OOB
            const bool rv = (t >= 0) && (h >= 0);
            const int tc = t > 0 ? t : 0;
            const int hc = h > 0 ? h : 0;
            rowoff[r] = (tc * HH + hc) * WW;

            const float* ep = g_emap + ((size_t)n * TT + tc) * (HH * WW) + (size_t)hc * WW;
            const int wbase = 2 * wl - 1;
            float e_m1 = (rv && act && wbase >= 0) ? ep[wbase] : 0.f;
            float e_0  = (rv && act) ? ep[2 * wl]     : 0.f;
            float e_1  = (rv && act) ? ep[2 * wl + 1] : 0.f;
            ewm[r] = e_m1;
            ewp[r] = ((unsigned long long)__float_as_uint(e_1) << 32) | __float_as_uint(e_0);
            dsum += e_m1 + e_0 + e_1;
        }
    }
    const float rden = act ? (1.0f / dsum) : 0.f;

    const float* basep = vw + (size_t)n * CC * PLANE + 2 * wl;
    float* outb = out + ((((size_t)n * CC) * TP + tp) * HP + hp) * WP + lane;

    for (int c = threadIdx.y; c < CC; c += 8) {
        const float* p = basep + (size_t)c * PLANE;
        unsigned long long acc = 0ull;
        float accs = 0.f;
#pragma unroll
        for (int r = 0; r < 9; r++) {
            unsigned long long x =
                act ? __ldg((const unsigned long long*)(p + rowoff[r])) : 0ull;
            float xy = hi32(x);                               // vw[2w'+1]
            float xm1 = __shfl_up_sync(0xffffffffu, xy, 1);   // vw[2w'-1] from lane-1
            acc = fma2(ewp[r], x, acc);
            accs = fmaf(xm1, ewm[r], accs);
        }
        if (act) {
            float s = lo32(acc) + hi32(acc) + accs;
            outb[(size_t)c * OPLANE] = s * rden;
        }
    }
}

extern "C" void kernel_launch(void* const* d_in, const int* in_sizes, int n_in,
                              void* d_out, int out_size) {
    const float* a0 = (const float*)d_in[0];
    const float* a1 = (const float*)d_in[1];
    // vw is the big tensor (51,380,224 elems); w is 16,384 elems.
    const float* vw   = (in_sizes[0] > in_sizes[1]) ? a0 : a1;
    const float* wmat = (in_sizes[0] > in_sizes[1]) ? a1 : a0;
    float* out = (float*)d_out;

    emap_kernel<<<dim3(HH / 4, TT, NB), dim3(32, 4)>>>(vw, wmat);
    pool_kernel<<<dim3(HP, TP, NB), dim3(32, 8)>>>(vw, out);
}

// round 2
// speedup vs baseline: 1.5549x; 1.5549x over previous
#include <cuda_runtime.h>
#include <math.h>

// Problem dims (fixed by the dataset)
#define NB 4
#define CC 256
#define TT 16
#define HH 56
#define WW 56
#define KK 16
#define TP 8
#define HP 28
#define WP 28
#define PLANE (TT*HH*WW)        // 50176, channel stride in vw
#define OPLANE (TP*HP*WP)       // 6272, channel stride in out

// Scratch: exp map, [N, T, H, W]
__device__ float g_emap[NB * TT * HH * WW];

__device__ __forceinline__ unsigned long long fma2(unsigned long long a,
                                                   unsigned long long b,
                                                   unsigned long long c) {
    unsigned long long d;
    asm("fma.rn.f32x2 %0, %1, %2, %3;" : "=l"(d) : "l"(a), "l"(b), "l"(c));
    return d;
}

__device__ __forceinline__ float lo32(unsigned long long v) {
    return __uint_as_float((unsigned)v);
}
__device__ __forceinline__ float hi32(unsigned long long v) {
    return __uint_as_float((unsigned)(v >> 32));
}

// ---------------------------------------------------------------------------
// Kernel 1: emap[n,t,h,w] = exp( max_k( sum_c w[n,k,c]*vw[n,c,t,h,w] ) / 16 )
// grid (H/4=14, T=16, N=4), block (32,4): one warp per (n,t,h) row.
// Each lane handles a pair of w positions (2*lane, 2*lane+1) packed in f32x2.
// ---------------------------------------------------------------------------
__global__ __launch_bounds__(128) void emap_kernel(const float* __restrict__ vw,
                                                   const float* __restrict__ wmat) {
    __shared__ unsigned long long wsp[CC * KK];  // [c][k], each {s,s} packed

    const int n = blockIdx.z;
    const int t = blockIdx.y;
    const int h = blockIdx.x * 4 + threadIdx.y;
    const int tid = threadIdx.y * 32 + threadIdx.x;

    // Load weights for this n into smem, duplicated into both f32x2 halves.
    const float* wn = wmat + (size_t)n * KK * CC;   // layout [k][c]
    for (int j = tid; j < KK * CC; j += 128) {
        int k = j >> 8;        // j = k*256 + c
        int c = j & 255;
        unsigned int si = __float_as_uint(wn[j]);
        wsp[c * KK + k] = ((unsigned long long)si << 32) | si;
    }
    __syncthreads();

    const int lane = threadIdx.x;
    if (lane >= 28) return;  // 28 pairs cover W=56

    // c=0 address for this (n,t,h) row at w = 2*lane
    size_t base = ((size_t)n * CC * TT + t) * (HH * WW) + (size_t)h * WW + 2 * lane;
    const unsigned long long* src = (const unsigned long long*)(vw + base);

    unsigned long long acc[KK];
#pragma unroll
    for (int k = 0; k < KK; k++) acc[k] = 0ull;

    const ulonglong2* wv = (const ulonglong2*)wsp;

    // Batch 8 loads per group for deep MLP, then consume.
#pragma unroll 2
    for (int c0 = 0; c0 < CC; c0 += 8) {
        unsigned long long x[8];
#pragma unroll
        for (int u = 0; u < 8; u++)
            x[u] = __ldg(src + (size_t)u * (PLANE / 2));
        src += 8 * (size_t)(PLANE / 2);
#pragma unroll
        for (int u = 0; u < 8; u++) {
#pragma unroll
            for (int kk = 0; kk < KK / 2; kk++) {
                ulonglong2 wp = wv[(c0 + u) * (KK / 2) + kk];
                acc[2 * kk]     = fma2(wp.x, x[u], acc[2 * kk]);
                acc[2 * kk + 1] = fma2(wp.y, x[u], acc[2 * kk + 1]);
            }
        }
    }

    float m0 = -3.4e38f, m1 = -3.4e38f;
#pragma unroll
    for (int k = 0; k < KK; k++) {
        m0 = fmaxf(m0, lo32(acc[k]));
        m1 = fmaxf(m1, hi32(acc[k]));
    }
    // sqrt(C) = 16 exactly
    float e0 = expf(m0 * 0.0625f);
    float e1 = expf(m1 * 0.0625f);

    size_t eidx = (((size_t)n * TT + t) * HH + h) * WW + 2 * lane;
    *(float2*)(g_emap + eidx) = make_float2(e0, e1);
}

// ---------------------------------------------------------------------------
// Kernel 2: out[n,c,t',h',w'] = sum_{window} vw*emap / sum_{window} emap
// Window: t in 2t'-1..2t'+1, h in 2h'-1..2h'+1, w in 2w'-1..2w'+1 (zero pad).
// grid (HP=28, TP=8, N=4), block (32,8): lane = w', y = channel group.
// 27 emap weights hoisted to registers (channel-invariant). Each thread now
// processes TWO channels per iteration (18 LDG.64 in flight, 2 indep FMA
// chains) and fetches the w-1 element with a scalar L1-hit LDG instead of a
// SHFL (removes the 26-cyc cross-lane dependency).
// ---------------------------------------------------------------------------
__global__ __launch_bounds__(256, 4) void pool_kernel(const float* __restrict__ vw,
                                                      float* __restrict__ out) {
    const int n  = blockIdx.z;
    const int tp = blockIdx.y;
    const int hp = blockIdx.x;
    const int lane = threadIdx.x;
    const int wl = lane < 27 ? lane : 27;  // clamp for safe address math
    const bool act = (lane < 28);

    float ewm[9];                 // weight for w = 2w'-1
    unsigned long long ewp[9];    // packed weights for w = 2w', 2w'+1
    int rowoff[9];                // (t*H + h)*W offsets (clamped)
    float dsum = 0.f;

#pragma unroll
    for (int dt = 0; dt < 3; dt++) {
#pragma unroll
        for (int dh = 0; dh < 3; dh++) {
            const int r = dt * 3 + dh;
            const int t = 2 * tp - 1 + dt;   // max 15, only -1 possible OOB
            const int h = 2 * hp - 1 + dh;   // max 55, only -1 possible OOB
            const bool rv = (t >= 0) && (h >= 0);
            const int tc = t > 0 ? t : 0;
            const int hc = h > 0 ? h : 0;
            rowoff[r] = (tc * HH + hc) * WW;

            const float* ep = g_emap + ((size_t)n * TT + tc) * (HH * WW) + (size_t)hc * WW;
            const int wbase = 2 * wl - 1;
            float e_m1 = (rv && wbase >= 0) ? ep[wbase] : 0.f;
            float e_0  = rv ? ep[2 * wl]     : 0.f;
            float e_1  = rv ? ep[2 * wl + 1] : 0.f;
            ewm[r] = e_m1;
            ewp[r] = ((unsigned long long)__float_as_uint(e_1) << 32) | __float_as_uint(e_0);
            dsum += e_m1 + e_0 + e_1;
        }
    }
    const float rden = 1.0f / dsum;

    // Offset of the w-1 scalar relative to the pair base (clamped to 0 for
    // lane 0 — its weight ewm is 0 there, and vw[...+0] is finite).
    const int off_m1 = (wl > 0) ? -1 : 0;

    const float* basep = vw + (size_t)n * CC * PLANE + 2 * wl;
    float* outb = out + ((((size_t)n * CC) * TP + tp) * HP + hp) * WP + lane;

    // Two channels per iteration: c0 and c0+1; threads stride by 16.
    for (int c0 = threadIdx.y * 2; c0 < CC; c0 += 16) {
        const float* pa = basep + (size_t)c0 * PLANE;
        const float* pb = pa + PLANE;
        unsigned long long accA = 0ull, accB = 0ull;
        float sA = 0.f, sB = 0.f;
#pragma unroll
        for (int r = 0; r < 9; r++) {
            const float* ra = pa + rowoff[r];
            const float* rb = pb + rowoff[r];
            unsigned long long xa = __ldg((const unsigned long long*)ra);
            unsigned long long xb = __ldg((const unsigned long long*)rb);
            float ma = __ldg(ra + off_m1);
            float mb = __ldg(rb + off_m1);
            accA = fma2(ewp[r], xa, accA);
            accB = fma2(ewp[r], xb, accB);
            sA = fmaf(ma, ewm[r], sA);
            sB = fmaf(mb, ewm[r], sB);
        }
        if (act) {
            outb[(size_t)c0 * OPLANE]       = (lo32(accA) + hi32(accA) + sA) * rden;
            outb[(size_t)(c0 + 1) * OPLANE] = (lo32(accB) + hi32(accB) + sB) * rden;
        }
    }
}

extern "C" void kernel_launch(void* const* d_in, const int* in_sizes, int n_in,
                              void* d_out, int out_size) {
    const float* a0 = (const float*)d_in[0];
    const float* a1 = (const float*)d_in[1];
    // vw is the big tensor (51,380,224 elems); w is 16,384 elems.
    const float* vw   = (in_sizes[0] > in_sizes[1]) ? a0 : a1;
    const float* wmat = (in_sizes[0] > in_sizes[1]) ? a1 : a0;
    float* out = (float*)d_out;

    emap_kernel<<<dim3(HH / 4, TT, NB), dim3(32, 4)>>>(vw, wmat);
    pool_kernel<<<dim3(HP, TP, NB), dim3(32, 8)>>>(vw, out);
}

// round 3
// speedup vs baseline: 1.7079x; 1.0984x over previous
#include <cuda_runtime.h>
#include <math.h>

// Problem dims (fixed by the dataset)
#define NB 4
#define CC 256
#define TT 16
#define HH 56
#define WW 56
#define KK 16
#define TP 8
#define HP 28
#define WP 28
#define PLANE (TT*HH*WW)        // 50176, channel stride in vw
#define OPLANE (TP*HP*WP)       // 6272, channel stride in out
#define SPLANE (HH*WW)          // 3136 spatial points per (n,t)

// Scratch: exp map, [N, T, H, W]
__device__ float g_emap[NB * TT * HH * WW];

__device__ __forceinline__ unsigned long long fma2(unsigned long long a,
                                                   unsigned long long b,
                                                   unsigned long long c) {
    unsigned long long d;
    asm("fma.rn.f32x2 %0, %1, %2, %3;" : "=l"(d) : "l"(a), "l"(b), "l"(c));
    return d;
}

__device__ __forceinline__ float lo32(unsigned long long v) {
    return __uint_as_float((unsigned)v);
}
__device__ __forceinline__ float hi32(unsigned long long v) {
    return __uint_as_float((unsigned)(v >> 32));
}

// ---------------------------------------------------------------------------
// Kernel 1: emap[n,t,h,w] = exp( max_k( sum_c w[n,k,c]*vw[n,c,t,h,w] ) / 16 )
// K is split across half-warps: lane = 16*khalf + pairIdx. Each lane keeps
// only 8 accumulator pairs (16 regs), so an x[8] load batch fits without
// spills. Duplicate addresses across the two half-warps are dedup'd by the
// LSU. Halves are merged with one shfl_xor(16) before exp.
// grid (14, 16, 4), block (32,7): 7 warps x 16 pairs = 112 pairs / block;
// 14 blocks cover the 1568 pairs of one (n,t) spatial plane.
// ---------------------------------------------------------------------------
__global__ __launch_bounds__(224) void emap_kernel(const float* __restrict__ vw,
                                                   const float* __restrict__ wmat) {
    __shared__ unsigned long long wsp[CC * KK];  // [c][k], each {s,s} packed

    const int n = blockIdx.z;
    const int t = blockIdx.y;
    const int tid = threadIdx.y * 32 + threadIdx.x;

    // Load weights for this n into smem, duplicated into both f32x2 halves.
    const float* wn = wmat + (size_t)n * KK * CC;   // layout [k][c]
    for (int j = tid; j < KK * CC; j += 224) {
        int k = j >> 8;        // j = k*256 + c
        int c = j & 255;
        unsigned int si = __float_as_uint(wn[j]);
        wsp[c * KK + k] = ((unsigned long long)si << 32) | si;
    }
    __syncthreads();

    const int lane  = threadIdx.x;
    const int khalf = lane >> 4;                       // 0 or 1
    const int pair  = blockIdx.x * 112 + threadIdx.y * 16 + (lane & 15);

    // c=0 address for this (n,t) plane at spatial pair index `pair`
    size_t base = ((size_t)n * CC * TT + t) * SPLANE + 2 * pair;
    const unsigned long long* src = (const unsigned long long*)(vw + base);

    unsigned long long acc[8];
#pragma unroll
    for (int k = 0; k < 8; k++) acc[k] = 0ull;

    const ulonglong2* wv = (const ulonglong2*)wsp;

    for (int c0 = 0; c0 < CC; c0 += 8) {
        unsigned long long x[8];
#pragma unroll
        for (int u = 0; u < 8; u++)
            x[u] = __ldg(src + (size_t)u * (PLANE / 2));
        src += 8 * (size_t)(PLANE / 2);
#pragma unroll
        for (int u = 0; u < 8; u++) {
#pragma unroll
            for (int j = 0; j < 4; j++) {
                ulonglong2 wp = wv[(c0 + u) * (KK / 2) + khalf * 4 + j];
                acc[2 * j]     = fma2(wp.x, x[u], acc[2 * j]);
                acc[2 * j + 1] = fma2(wp.y, x[u], acc[2 * j + 1]);
            }
        }
    }

    float m0 = -3.4e38f, m1 = -3.4e38f;
#pragma unroll
    for (int k = 0; k < 8; k++) {
        m0 = fmaxf(m0, lo32(acc[k]));
        m1 = fmaxf(m1, hi32(acc[k]));
    }
    // merge the two k-halves
    m0 = fmaxf(m0, __shfl_xor_sync(0xffffffffu, m0, 16));
    m1 = fmaxf(m1, __shfl_xor_sync(0xffffffffu, m1, 16));

    if (khalf == 0) {
        // sqrt(C) = 16 exactly
        float e0 = expf(m0 * 0.0625f);
        float e1 = expf(m1 * 0.0625f);
        size_t eidx = ((size_t)n * TT + t) * SPLANE + 2 * pair;
        *(float2*)(g_emap + eidx) = make_float2(e0, e1);
    }
}

// ---------------------------------------------------------------------------
// Kernel 2: out[n,c,t',h',w'] = sum_{window} vw*emap / sum_{window} emap
// Decomposition: out_i = S_i + X_{i-1}, where
//   S_i = sum_r ( e[2i]*v[2i] + e[2i+1]*v[2i+1] )   (fma2 on the pair at i)
//   X_i = sum_r   e[2i+1]*v[2i+1]                   (cross term for out i+1)
// X moves one lane right via a single shfl_up per channel AFTER the r-loop,
// so the load path has no cross-lane dependency and no scalar LDGs:
// 9 LDG.64 per output-channel (was 18 LSU ops). Same trick for the denom.
// grid (HP, TP, NB), block (32,8), 2 channels per thread-iteration.
// ---------------------------------------------------------------------------
__global__ __launch_bounds__(256, 5) void pool_kernel(const float* __restrict__ vw,
                                                      float* __restrict__ out) {
    const int n  = blockIdx.z;
    const int tp = blockIdx.y;
    const int hp = blockIdx.x;
    const int lane = threadIdx.x;
    const int wl = lane < 27 ? lane : 27;  // clamp for safe address math
    const bool act = (lane < 28);

    unsigned long long ewp[9];    // packed weights for w = 2w', 2w'+1
    int rowoff[9];                // (t*H + h)*W offsets (clamped)
    float dpair = 0.f, dx = 0.f;

#pragma unroll
    for (int dt = 0; dt < 3; dt++) {
#pragma unroll
        for (int dh = 0; dh < 3; dh++) {
            const int r = dt * 3 + dh;
            const int t = 2 * tp - 1 + dt;   // max 15, only -1 possible OOB
            const int h = 2 * hp - 1 + dh;   // max 55, only -1 possible OOB
            const bool rv = (t >= 0) && (h >= 0);
            const int tc = t > 0 ? t : 0;
            const int hc = h > 0 ? h : 0;
            rowoff[r] = (tc * HH + hc) * WW;

            const float* ep = g_emap + ((size_t)n * TT + tc) * SPLANE + (size_t)hc * WW;
            float e_0 = rv ? ep[2 * wl]     : 0.f;
            float e_1 = rv ? ep[2 * wl + 1] : 0.f;
            ewp[r] = ((unsigned long long)__float_as_uint(e_1) << 32) | __float_as_uint(e_0);
            dpair += e_0 + e_1;
            dx += e_1;
        }
    }
    float dxm1 = __shfl_up_sync(0xffffffffu, dx, 1);
    if (lane == 0) dxm1 = 0.f;
    const float rden = 1.0f / (dpair + dxm1);

    const float* basep = vw + (size_t)n * CC * PLANE + 2 * wl;
    float* outb = out + ((((size_t)n * CC) * TP + tp) * HP + hp) * WP + lane;

    // Two channels per iteration: c0 and c0+1; threads stride by 16.
    for (int c0 = threadIdx.y * 2; c0 < CC; c0 += 16) {
        const float* pa = basep + (size_t)c0 * PLANE;
        const float* pb = pa + PLANE;
        unsigned long long accA = 0ull, accB = 0ull;
        float XA = 0.f, XB = 0.f;
#pragma unroll
        for (int r = 0; r < 9; r++) {
            unsigned long long xa = __ldg((const unsigned long long*)(pa + rowoff[r]));
            unsigned long long xb = __ldg((const unsigned long long*)(pb + rowoff[r]));
            accA = fma2(ewp[r], xa, accA);
            accB = fma2(ewp[r], xb, accB);
            XA = fmaf(hi32(ewp[r]), hi32(xa), XA);
            XB = fmaf(hi32(ewp[r]), hi32(xb), XB);
        }
        float XAm1 = __shfl_up_sync(0xffffffffu, XA, 1);
        float XBm1 = __shfl_up_sync(0xffffffffu, XB, 1);
        if (lane == 0) { XAm1 = 0.f; XBm1 = 0.f; }
        if (act) {
            outb[(size_t)c0 * OPLANE]       = (lo32(accA) + hi32(accA) + XAm1) * rden;
            outb[(size_t)(c0 + 1) * OPLANE] = (lo32(accB) + hi32(accB) + XBm1) * rden;
        }
    }
}

extern "C" void kernel_launch(void* const* d_in, const int* in_sizes, int n_in,
                              void* d_out, int out_size) {
    const float* a0 = (const float*)d_in[0];
    const float* a1 = (const float*)d_in[1];
    // vw is the big tensor (51,380,224 elems); w is 16,384 elems.
    const float* vw   = (in_sizes[0] > in_sizes[1]) ? a0 : a1;
    const float* wmat = (in_sizes[0] > in_sizes[1]) ? a1 : a0;
    float* out = (float*)d_out;

    emap_kernel<<<dim3(14, TT, NB), dim3(32, 7)>>>(vw, wmat);
    pool_kernel<<<dim3(HP, TP, NB), dim3(32, 8)>>>(vw, out);
}